// round 1
// baseline (speedup 1.0000x reference)
#include <cuda_runtime.h>
#include <cstdint>

// Fixed problem geometry
#define BS   4
#define NQ   4000
#define EMB  256
#define NH   8
#define NLV  4
#define NP   4
#define HD   32
#define NV   13294            // 100*100 + 50*50 + 25*25 + 13*13
#define M1   (BS * NV)        // 53176 rows for value projection
#define BQ   (BS * NQ)        // 16000

// Scratch (device globals; no cudaMalloc allowed)
__device__ float g_v[(size_t)BS * NV * EMB];      // projected value, [b][t][h*32+d]
__device__ float g_off[(size_t)BQ * EMB];         // sampling offsets, [bq][h*32+(l*4+p)*2+c]
__device__ float g_attn[(size_t)BQ * (NH * NLV * NP)]; // attn logits, [bq][h*16+(l*4+p)]
__device__ float g_mid[(size_t)BQ * EMB];         // sampled output before W_out

// ---------------------------------------------------------------------------
// Generic tiled SGEMM: C[M,N] = A[M,K] @ B[K,N] + bias[N]
// 64x64 tile, BK=16, 256 threads, 4x4 per-thread microtile.
// Requires: N % 64 == 0, K % 16 == 0, 16B-aligned rows (K % 4 == 0). M guarded.
// ---------------------------------------------------------------------------
__global__ __launch_bounds__(256) void sgemm_bias(
    const float* __restrict__ A, const float* __restrict__ B,
    const float* __restrict__ bias, float* __restrict__ C,
    int M, int N, int K)
{
    __shared__ float As[16][65];   // padded: conflict-free transposed stores
    __shared__ float Bs[16][64];

    const int tid  = threadIdx.x;
    const int row0 = blockIdx.y * 64;
    const int col0 = blockIdx.x * 64;
    const int ty = tid >> 4;       // 0..15
    const int tx = tid & 15;       // 0..15

    // A-tile load mapping: each thread loads a float4 from one row
    const int am = tid >> 2;            // 0..63
    const int ak = (tid & 3) * 4;       // 0,4,8,12
    // B-tile load mapping: each thread loads a float4 from one k-row
    const int bk = tid >> 4;            // 0..15
    const int bn = (tid & 15) * 4;      // 0..60

    float acc[4][4] = {};

    for (int k0 = 0; k0 < K; k0 += 16) {
        const int gr = row0 + am;
        float4 av = make_float4(0.f, 0.f, 0.f, 0.f);
        if (gr < M)
            av = *reinterpret_cast<const float4*>(&A[(size_t)gr * K + k0 + ak]);
        As[ak + 0][am] = av.x;
        As[ak + 1][am] = av.y;
        As[ak + 2][am] = av.z;
        As[ak + 3][am] = av.w;

        float4 bv = *reinterpret_cast<const float4*>(
            &B[(size_t)(k0 + bk) * N + col0 + bn]);
        *reinterpret_cast<float4*>(&Bs[bk][bn]) = bv;

        __syncthreads();

        #pragma unroll
        for (int k = 0; k < 16; k++) {
            float a0 = As[k][ty * 4 + 0];
            float a1 = As[k][ty * 4 + 1];
            float a2 = As[k][ty * 4 + 2];
            float a3 = As[k][ty * 4 + 3];
            float4 b4 = *reinterpret_cast<const float4*>(&Bs[k][tx * 4]);
            acc[0][0] += a0 * b4.x; acc[0][1] += a0 * b4.y; acc[0][2] += a0 * b4.z; acc[0][3] += a0 * b4.w;
            acc[1][0] += a1 * b4.x; acc[1][1] += a1 * b4.y; acc[1][2] += a1 * b4.z; acc[1][3] += a1 * b4.w;
            acc[2][0] += a2 * b4.x; acc[2][1] += a2 * b4.y; acc[2][2] += a2 * b4.z; acc[2][3] += a2 * b4.w;
            acc[3][0] += a3 * b4.x; acc[3][1] += a3 * b4.y; acc[3][2] += a3 * b4.z; acc[3][3] += a3 * b4.w;
        }
        __syncthreads();
    }

    #pragma unroll
    for (int i = 0; i < 4; i++) {
        const int gr = row0 + ty * 4 + i;
        if (gr >= M) continue;
        #pragma unroll
        for (int j = 0; j < 4; j++) {
            const int gc = col0 + tx * 4 + j;
            C[(size_t)gr * N + gc] = acc[i][j] + bias[gc];
        }
    }
}

// ---------------------------------------------------------------------------
// Sampling kernel: one warp per (b, q, h). Lane = channel d (HD=32).
// Softmax over 16 logits computed redundantly per lane (scalar, cheap).
// Bilinear gathers are 128B-coalesced across the warp.
// ---------------------------------------------------------------------------
__global__ __launch_bounds__(256) void ms_deform_sample(
    const float* __restrict__ refp_g, const float* __restrict__ off_g,
    const float* __restrict__ attn_g, const float* __restrict__ v_g,
    float* __restrict__ mid_g)
{
    const int lane = threadIdx.x & 31;
    const int wrp  = threadIdx.x >> 5;
    const int task = blockIdx.x * 8 + wrp;       // 0 .. 128000-1
    if (task >= BQ * NH) return;

    const int h  = task & 7;
    const int bq = task >> 3;                    // b*NQ + q
    const int b  = bq / NQ;

    // --- softmax over the 16 (level, point) logits for this head ---
    const float* lg = attn_g + (size_t)bq * (NH * 16) + h * 16;
    float wgt[16];
    float mx = -1e30f;
    #pragma unroll
    for (int i = 0; i < 16; i++) { wgt[i] = lg[i]; mx = fmaxf(mx, wgt[i]); }
    float s = 0.f;
    #pragma unroll
    for (int i = 0; i < 16; i++) { wgt[i] = __expf(wgt[i] - mx); s += wgt[i]; }
    const float inv = 1.f / s;

    const float* offp = off_g + (size_t)bq * EMB + h * 32;   // [l*4+p][2]
    const float* refq = refp_g + (size_t)bq * (NLV * 2);     // [l][2]

    const int HH[4] = {100, 50, 25, 13};
    const int WW[4] = {100, 50, 25, 13};
    const int ST[4] = {0, 10000, 12500, 13125};

    float acc = 0.f;

    #pragma unroll
    for (int l = 0; l < NLV; l++) {
        const int H = HH[l], W = WW[l];
        const float fW = (float)W, fH = (float)H;
        const float rx = refq[l * 2 + 0];
        const float ry = refq[l * 2 + 1];
        const float* vbase = v_g + ((size_t)b * NV + ST[l]) * EMB + h * 32 + lane;

        #pragma unroll
        for (int p = 0; p < NP; p++) {
            const float ox = offp[(l * 4 + p) * 2 + 0];
            const float oy = offp[(l * 4 + p) * 2 + 1];
            // replicate reference math exactly: (r + o/norm)*dim - 0.5
            const float x = (rx + ox / fW) * fW - 0.5f;
            const float y = (ry + oy / fH) * fH - 0.5f;
            const float aw = wgt[l * 4 + p] * inv;

            const float x0f = floorf(x), y0f = floorf(y);
            const float fx = x - x0f, fy = y - y0f;
            const int ix = (int)x0f, iy = (int)y0f;

            const float w00 = (1.f - fx) * (1.f - fy) * aw;
            const float w10 = fx * (1.f - fy) * aw;
            const float w01 = (1.f - fx) * fy * aw;
            const float w11 = fx * fy * aw;

            const bool vx0 = (ix >= 0) && (ix < W);
            const bool vx1 = (ix + 1 >= 0) && (ix + 1 < W);
            const bool vy0 = (iy >= 0) && (iy < H);
            const bool vy1 = (iy + 1 >= 0) && (iy + 1 < H);

            if (vy0) {
                const float* r0 = vbase + (size_t)(iy * W) * EMB;
                if (vx0) acc += w00 * r0[(size_t)ix * EMB];
                if (vx1) acc += w10 * r0[(size_t)(ix + 1) * EMB];
            }
            if (vy1) {
                const float* r1 = vbase + (size_t)((iy + 1) * W) * EMB;
                if (vx0) acc += w01 * r1[(size_t)ix * EMB];
                if (vx1) acc += w11 * r1[(size_t)(ix + 1) * EMB];
            }
        }
    }

    mid_g[(size_t)bq * EMB + h * 32 + lane] = acc;
}

// ---------------------------------------------------------------------------
extern "C" void kernel_launch(void* const* d_in, const int* in_sizes, int n_in,
                              void* d_out, int out_size)
{
    const float* query  = (const float*)d_in[0];
    const float* value  = (const float*)d_in[1];
    const float* refp   = (const float*)d_in[2];
    // d_in[3] = spatial_shapes (int32) — geometry hardcoded
    const float* W_off  = (const float*)d_in[4];
    const float* b_off  = (const float*)d_in[5];
    const float* W_attn = (const float*)d_in[6];
    const float* b_attn = (const float*)d_in[7];
    const float* W_val  = (const float*)d_in[8];
    const float* b_val  = (const float*)d_in[9];
    const float* W_out  = (const float*)d_in[10];
    const float* b_out  = (const float*)d_in[11];
    float* out = (float*)d_out;

    float *pv, *poff, *pattn, *pmid;
    cudaGetSymbolAddress((void**)&pv,    g_v);
    cudaGetSymbolAddress((void**)&poff,  g_off);
    cudaGetSymbolAddress((void**)&pattn, g_attn);
    cudaGetSymbolAddress((void**)&pmid,  g_mid);

    // 1. value projection: [53176,256] @ [256,256]
    sgemm_bias<<<dim3(EMB / 64, (M1 + 63) / 64), 256>>>(
        value, W_val, b_val, pv, M1, EMB, EMB);

    // 2a. sampling offsets: [16000,256] @ [256,256]
    sgemm_bias<<<dim3(EMB / 64, BQ / 64), 256>>>(
        query, W_off, b_off, poff, BQ, EMB, EMB);

    // 2b. attention logits: [16000,256] @ [256,128]
    sgemm_bias<<<dim3(128 / 64, BQ / 64), 256>>>(
        query, W_attn, b_attn, pattn, BQ, 128, EMB);

    // 3. softmax + bilinear sampling + weighted accumulate
    ms_deform_sample<<<(BQ * NH) / 8, 256>>>(refp, poff, pattn, pv, pmid);

    // 4. output projection: [16000,256] @ [256,256]
    sgemm_bias<<<dim3(EMB / 64, BQ / 64), 256>>>(
        pmid, W_out, b_out, out, BQ, EMB, EMB);
}

// round 2
// speedup vs baseline: 1.3628x; 1.3628x over previous
#include <cuda_runtime.h>
#include <cstdint>

// Fixed problem geometry
#define BS   4
#define NQ   4000
#define EMB  256
#define NH   8
#define NLV  4
#define NP   4
#define HD   32
#define NV   13294            // 100*100 + 50*50 + 25*25 + 13*13
#define M1   (BS * NV)        // 53176 rows for value projection
#define BQ   (BS * NQ)        // 16000

// Scratch (device globals; no cudaMalloc allowed)
__device__ float g_v[(size_t)BS * NV * EMB];
__device__ float g_off[(size_t)BQ * EMB];
__device__ float g_attn[(size_t)BQ * (NH * NLV * NP)];
__device__ float g_mid[(size_t)BQ * EMB];

// ---------------------------------------------------------------------------
// Generic tiled SGEMM: C[M,N] = A[M,K] @ B[K,N] + bias[N]
// ---------------------------------------------------------------------------
__global__ __launch_bounds__(256) void sgemm_bias(
    const float* __restrict__ A, const float* __restrict__ B,
    const float* __restrict__ bias, float* __restrict__ C,
    int M, int N, int K)
{
    __shared__ float As[16][65];
    __shared__ float Bs[16][64];

    const int tid  = threadIdx.x;
    const int row0 = blockIdx.y * 64;
    const int col0 = blockIdx.x * 64;
    const int ty = tid >> 4;
    const int tx = tid & 15;

    const int am = tid >> 2;
    const int ak = (tid & 3) * 4;
    const int bk = tid >> 4;
    const int bn = (tid & 15) * 4;

    float acc[4][4] = {};

    for (int k0 = 0; k0 < K; k0 += 16) {
        const int gr = row0 + am;
        float4 av = make_float4(0.f, 0.f, 0.f, 0.f);
        if (gr < M)
            av = *reinterpret_cast<const float4*>(&A[(size_t)gr * K + k0 + ak]);
        As[ak + 0][am] = av.x;
        As[ak + 1][am] = av.y;
        As[ak + 2][am] = av.z;
        As[ak + 3][am] = av.w;

        float4 bv = *reinterpret_cast<const float4*>(
            &B[(size_t)(k0 + bk) * N + col0 + bn]);
        *reinterpret_cast<float4*>(&Bs[bk][bn]) = bv;

        __syncthreads();

        #pragma unroll
        for (int k = 0; k < 16; k++) {
            float a0 = As[k][ty * 4 + 0];
            float a1 = As[k][ty * 4 + 1];
            float a2 = As[k][ty * 4 + 2];
            float a3 = As[k][ty * 4 + 3];
            float4 b4 = *reinterpret_cast<const float4*>(&Bs[k][tx * 4]);
            acc[0][0] += a0 * b4.x; acc[0][1] += a0 * b4.y; acc[0][2] += a0 * b4.z; acc[0][3] += a0 * b4.w;
            acc[1][0] += a1 * b4.x; acc[1][1] += a1 * b4.y; acc[1][2] += a1 * b4.z; acc[1][3] += a1 * b4.w;
            acc[2][0] += a2 * b4.x; acc[2][1] += a2 * b4.y; acc[2][2] += a2 * b4.z; acc[2][3] += a2 * b4.w;
            acc[3][0] += a3 * b4.x; acc[3][1] += a3 * b4.y; acc[3][2] += a3 * b4.z; acc[3][3] += a3 * b4.w;
        }
        __syncthreads();
    }

    #pragma unroll
    for (int i = 0; i < 4; i++) {
        const int gr = row0 + ty * 4 + i;
        if (gr >= M) continue;
        #pragma unroll
        for (int j = 0; j < 4; j++) {
            const int gc = col0 + tx * 4 + j;
            C[(size_t)gr * N + gc] = acc[i][j] + bias[gc];
        }
    }
}

// ---------------------------------------------------------------------------
// Sampling kernel, two-phase:
//  Phase 1: 128 threads; thread = (local task 0..7, point 0..15). Computes the
//           softmax weight, bilinear corner weights (validity folded in as
//           zero weight + clamped index) and 4 element offsets -> smem.
//  Phase 2: 8 warps; warp = local task, lane = channel. Streams 16 points as
//           2x LDS.128 + 4x LDG + 4x FFMA.
// ---------------------------------------------------------------------------
__constant__ int c_HH[4] = {100, 50, 25, 13};
__constant__ int c_ST[4] = {0, 10000, 12500, 13125};

__global__ __launch_bounds__(256) void ms_deform_sample(
    const float* __restrict__ refp_g, const float* __restrict__ off_g,
    const float* __restrict__ attn_g, const float* __restrict__ v_g,
    float* __restrict__ mid_g)
{
    __shared__ float4 s_w[8][16];
    __shared__ int4   s_o[8][16];

    const int tid = threadIdx.x;

    // ---------------- Phase 1 ----------------
    if (tid < 128) {
        const int wt = tid >> 4;            // local task 0..7
        const int pt = tid & 15;            // point 0..15
        const int task = blockIdx.x * 8 + wt;
        const int h  = task & 7;
        const int bq = task >> 3;

        // softmax weight for this point (redundant max/sum across 16 threads
        // of the same task, but fully parallel)
        const float* lg = attn_g + (size_t)bq * (NH * 16) + h * 16;
        float mx = -1e30f;
        #pragma unroll
        for (int i = 0; i < 16; i++) mx = fmaxf(mx, lg[i]);
        float s = 0.f;
        #pragma unroll
        for (int i = 0; i < 16; i++) s += __expf(lg[i] - mx);
        const float aw = __expf(lg[pt] - mx) / s;

        const int l = pt >> 2;
        const int W = c_HH[l];              // square levels: H == W
        const int H = W;
        const float fW = (float)W, fH = (float)H;

        const float rx = refp_g[(size_t)bq * (NLV * 2) + l * 2 + 0];
        const float ry = refp_g[(size_t)bq * (NLV * 2) + l * 2 + 1];
        const float ox = off_g[(size_t)bq * EMB + h * 32 + pt * 2 + 0];
        const float oy = off_g[(size_t)bq * EMB + h * 32 + pt * 2 + 1];

        // exact reference math: (r + o/norm)*dim - 0.5
        const float x = (rx + ox / fW) * fW - 0.5f;
        const float y = (ry + oy / fH) * fH - 0.5f;

        const float x0f = floorf(x), y0f = floorf(y);
        const float fx = x - x0f, fy = y - y0f;
        const int ix = (int)x0f, iy = (int)y0f;

        const float vx0 = (ix >= 0 && ix < W) ? 1.f : 0.f;
        const float vx1 = (ix + 1 >= 0 && ix + 1 < W) ? 1.f : 0.f;
        const float vy0 = (iy >= 0 && iy < H) ? 1.f : 0.f;
        const float vy1 = (iy + 1 >= 0 && iy + 1 < H) ? 1.f : 0.f;

        const int cx0 = min(max(ix, 0), W - 1);
        const int cx1 = min(max(ix + 1, 0), W - 1);
        const int cy0 = min(max(iy, 0), H - 1);
        const int cy1 = min(max(iy + 1, 0), H - 1);

        float4 w;
        w.x = (1.f - fx) * (1.f - fy) * aw * vx0 * vy0;
        w.y = fx * (1.f - fy) * aw * vx1 * vy0;
        w.z = (1.f - fx) * fy * aw * vx0 * vy1;
        w.w = fx * fy * aw * vx1 * vy1;

        const int base = c_ST[l];
        int4 o;
        o.x = (base + cy0 * W + cx0) * EMB;
        o.y = (base + cy0 * W + cx1) * EMB;
        o.z = (base + cy1 * W + cx0) * EMB;
        o.w = (base + cy1 * W + cx1) * EMB;

        s_w[wt][pt] = w;
        s_o[wt][pt] = o;
    }
    __syncthreads();

    // ---------------- Phase 2 ----------------
    const int lane = tid & 31;
    const int wrp  = tid >> 5;
    const int task = blockIdx.x * 8 + wrp;
    const int h  = task & 7;
    const int bq = task >> 3;
    const int b  = bq / NQ;

    const float* vt = v_g + ((size_t)b * NV) * EMB + h * 32 + lane;

    float acc = 0.f;
    #pragma unroll
    for (int pt = 0; pt < 16; pt++) {
        const float4 w = s_w[wrp][pt];
        const int4   o = s_o[wrp][pt];
        acc += w.x * __ldg(vt + o.x);
        acc += w.y * __ldg(vt + o.y);
        acc += w.z * __ldg(vt + o.z);
        acc += w.w * __ldg(vt + o.w);
    }

    mid_g[(size_t)bq * EMB + h * 32 + lane] = acc;
}

// ---------------------------------------------------------------------------
extern "C" void kernel_launch(void* const* d_in, const int* in_sizes, int n_in,
                              void* d_out, int out_size)
{
    const float* query  = (const float*)d_in[0];
    const float* value  = (const float*)d_in[1];
    const float* refp   = (const float*)d_in[2];
    const float* W_off  = (const float*)d_in[4];
    const float* b_off  = (const float*)d_in[5];
    const float* W_attn = (const float*)d_in[6];
    const float* b_attn = (const float*)d_in[7];
    const float* W_val  = (const float*)d_in[8];
    const float* b_val  = (const float*)d_in[9];
    const float* W_out  = (const float*)d_in[10];
    const float* b_out  = (const float*)d_in[11];
    float* out = (float*)d_out;

    float *pv, *poff, *pattn, *pmid;
    cudaGetSymbolAddress((void**)&pv,    g_v);
    cudaGetSymbolAddress((void**)&poff,  g_off);
    cudaGetSymbolAddress((void**)&pattn, g_attn);
    cudaGetSymbolAddress((void**)&pmid,  g_mid);

    // 1. value projection: [53176,256] @ [256,256]
    sgemm_bias<<<dim3(EMB / 64, (M1 + 63) / 64), 256>>>(
        value, W_val, b_val, pv, M1, EMB, EMB);

    // 2a. sampling offsets: [16000,256] @ [256,256]
    sgemm_bias<<<dim3(EMB / 64, BQ / 64), 256>>>(
        query, W_off, b_off, poff, BQ, EMB, EMB);

    // 2b. attention logits: [16000,256] @ [256,128]
    sgemm_bias<<<dim3(128 / 64, BQ / 64), 256>>>(
        query, W_attn, b_attn, pattn, BQ, 128, EMB);

    // 3. softmax + bilinear sampling + weighted accumulate
    ms_deform_sample<<<BQ * NH / 8, 256>>>(refp, poff, pattn, pv, pmid);

    // 4. output projection: [16000,256] @ [256,256]
    sgemm_bias<<<dim3(EMB / 64, BQ / 64), 256>>>(
        pmid, W_out, b_out, out, BQ, EMB, EMB);
}

// round 3
// speedup vs baseline: 2.8485x; 2.0902x over previous
#include <cuda_runtime.h>
#include <cstdint>

// Fixed problem geometry
#define BS   4
#define NQ   4000
#define EMB  256
#define NH   8
#define NLV  4
#define NP   4
#define HD   32
#define NV   13294            // 100*100 + 50*50 + 25*25 + 13*13
#define M1   (BS * NV)        // 53176 rows for value projection
#define BQ   (BS * NQ)        // 16000

// Scratch (device globals; no cudaMalloc allowed)
__device__ float g_v[(size_t)BS * NV * EMB];
__device__ float g_off[(size_t)BQ * EMB];
__device__ float g_attn[(size_t)BQ * (NH * NLV * NP)];
__device__ float g_mid[(size_t)BQ * EMB];

// ---------------------------------------------------------------------------
// tf32 tensor-core GEMM: C[M,N] = A[M,K=256] @ B[256,N] + bias[N]
// BM=128, BN=128, BK=16, 256 threads (8 warps: 4 along M x 2 along N),
// warp tile 32x64 via m16n8k8. cp.async double-buffered.
// smem strides: As row stride 20 floats (bank-conflict-free A-frag reads),
//               Bs row stride 136 floats (bank-conflict-free B-frag reads).
// ---------------------------------------------------------------------------
__device__ __forceinline__ uint32_t f2tf32(float f) {
    uint32_t u;
    asm("cvt.rna.tf32.f32 %0, %1;" : "=r"(u) : "f"(f));
    return u;
}

__device__ __forceinline__ void mma_tf32(float* c, const uint32_t* a,
                                         uint32_t b0, uint32_t b1) {
    asm volatile(
        "mma.sync.aligned.m16n8k8.row.col.f32.tf32.tf32.f32 "
        "{%0,%1,%2,%3},{%4,%5,%6,%7},{%8,%9},{%0,%1,%2,%3};"
        : "+f"(c[0]), "+f"(c[1]), "+f"(c[2]), "+f"(c[3])
        : "r"(a[0]), "r"(a[1]), "r"(a[2]), "r"(a[3]), "r"(b0), "r"(b1));
}

__device__ __forceinline__ void cpa16(uint32_t saddr, const float* g, bool p) {
    int sz = p ? 16 : 0;
    asm volatile("cp.async.cg.shared.global [%0], [%1], 16, %2;"
                 :: "r"(saddr), "l"(g), "r"(sz));
}

#define AS_STRIDE 20
#define BS_STRIDE 136

__global__ __launch_bounds__(256, 2) void gemm_tf32_bias(
    const float* __restrict__ A, const float* __restrict__ B,
    const float* __restrict__ bias, float* __restrict__ C,
    int M, int N)   // K = 256 fixed
{
    __shared__ __align__(16) float As[2][128][AS_STRIDE];
    __shared__ __align__(16) float Bs[2][16][BS_STRIDE];

    const int tid  = threadIdx.x;
    const int lane = tid & 31, warp = tid >> 5;
    const int gid  = lane >> 2, tig = lane & 3;
    const int row0 = blockIdx.y * 128;
    const int col0 = blockIdx.x * 128;

    const uint32_t asb = (uint32_t)__cvta_generic_to_shared(&As[0][0][0]);
    const uint32_t bsb = (uint32_t)__cvta_generic_to_shared(&Bs[0][0][0]);

    // loader mappings
    const int lar = tid >> 2;             // A row (0..63), +64 for second
    const int lak = (tid & 3) * 4;        // A k-offset in floats
    const int lbk = tid >> 5;             // B k-row (0..7), +8 for second
    const int lbn = (tid & 31) * 4;       // B n-offset in floats

    float acc[2][8][4] = {};

    auto load_stage = [&](int st, int kb) {
        const float* Ag = A + (size_t)row0 * 256 + kb * 16;
        cpa16(asb + (((st * 128 + lar) * AS_STRIDE + lak) << 2),
              Ag + (size_t)lar * 256 + lak, row0 + lar < M);
        cpa16(asb + (((st * 128 + lar + 64) * AS_STRIDE + lak) << 2),
              Ag + (size_t)(lar + 64) * 256 + lak, row0 + lar + 64 < M);
        const float* Bg = B + (size_t)(kb * 16) * N + col0;
        cpa16(bsb + (((st * 16 + lbk) * BS_STRIDE + lbn) << 2),
              Bg + (size_t)lbk * N + lbn, true);
        cpa16(bsb + (((st * 16 + lbk + 8) * BS_STRIDE + lbn) << 2),
              Bg + (size_t)(lbk + 8) * N + lbn, true);
    };

    load_stage(0, 0);
    asm volatile("cp.async.commit_group;" ::: "memory");

    const int wm = (warp & 3) * 32;
    const int wn = (warp >> 2) * 64;

    for (int kb = 0; kb < 16; kb++) {
        asm volatile("cp.async.wait_group 0;" ::: "memory");
        __syncthreads();
        if (kb + 1 < 16) {
            load_stage((kb + 1) & 1, kb + 1);
            asm volatile("cp.async.commit_group;" ::: "memory");
        }
        const int st = kb & 1;

        #pragma unroll
        for (int ks = 0; ks < 2; ks++) {
            const int kk = ks * 8;
            uint32_t a[2][4];
            #pragma unroll
            for (int mt = 0; mt < 2; mt++) {
                const int m0 = wm + mt * 16;
                a[mt][0] = f2tf32(As[st][m0 + gid][kk + tig]);
                a[mt][1] = f2tf32(As[st][m0 + gid + 8][kk + tig]);
                a[mt][2] = f2tf32(As[st][m0 + gid][kk + tig + 4]);
                a[mt][3] = f2tf32(As[st][m0 + gid + 8][kk + tig + 4]);
            }
            #pragma unroll
            for (int nt = 0; nt < 8; nt++) {
                const int nn = wn + nt * 8 + gid;
                uint32_t b0 = f2tf32(Bs[st][kk + tig][nn]);
                uint32_t b1 = f2tf32(Bs[st][kk + tig + 4][nn]);
                mma_tf32(acc[0][nt], a[0], b0, b1);
                mma_tf32(acc[1][nt], a[1], b0, b1);
            }
        }
        __syncthreads();
    }

    // epilogue
    #pragma unroll
    for (int mt = 0; mt < 2; mt++) {
        const int rbase = row0 + wm + mt * 16 + gid;
        #pragma unroll
        for (int nt = 0; nt < 8; nt++) {
            const int col = col0 + wn + nt * 8 + tig * 2;
            const float b0 = bias[col], b1 = bias[col + 1];
            if (rbase < M) {
                C[(size_t)rbase * N + col]     = acc[mt][nt][0] + b0;
                C[(size_t)rbase * N + col + 1] = acc[mt][nt][1] + b1;
            }
            if (rbase + 8 < M) {
                C[(size_t)(rbase + 8) * N + col]     = acc[mt][nt][2] + b0;
                C[(size_t)(rbase + 8) * N + col + 1] = acc[mt][nt][3] + b1;
            }
        }
    }
}

// ---------------------------------------------------------------------------
// Sampling kernel, two-phase.
//  Phase 1: 128 threads; thread = (local task, point): softmax weight +
//           bilinear corner weights (validity folded in) + 4 offsets -> smem.
//  Phase 2: 8 warps; warp = task. Lane covers 2 channels (float2), so the
//           warp processes 2 points per step -> half the LDG count.
// ---------------------------------------------------------------------------
__constant__ int c_HH[4] = {100, 50, 25, 13};
__constant__ int c_ST[4] = {0, 10000, 12500, 13125};

__global__ __launch_bounds__(256) void ms_deform_sample(
    const float* __restrict__ refp_g, const float* __restrict__ off_g,
    const float* __restrict__ attn_g, const float* __restrict__ v_g,
    float* __restrict__ mid_g)
{
    __shared__ float4 s_w[8][16];
    __shared__ int4   s_o[8][16];

    const int tid = threadIdx.x;

    // ---------------- Phase 1 ----------------
    if (tid < 128) {
        const int wt = tid >> 4;            // local task 0..7
        const int pt = tid & 15;            // point 0..15
        const int task = blockIdx.x * 8 + wt;
        const int h  = task & 7;
        const int bq = task >> 3;

        const float* lg = attn_g + (size_t)bq * (NH * 16) + h * 16;
        float mx = -1e30f;
        #pragma unroll
        for (int i = 0; i < 16; i++) mx = fmaxf(mx, lg[i]);
        float s = 0.f;
        #pragma unroll
        for (int i = 0; i < 16; i++) s += __expf(lg[i] - mx);
        const float aw = __expf(lg[pt] - mx) / s;

        const int l = pt >> 2;
        const int W = c_HH[l];
        const int H = W;
        const float fW = (float)W, fH = (float)H;

        const float rx = refp_g[(size_t)bq * (NLV * 2) + l * 2 + 0];
        const float ry = refp_g[(size_t)bq * (NLV * 2) + l * 2 + 1];
        const float ox = off_g[(size_t)bq * EMB + h * 32 + pt * 2 + 0];
        const float oy = off_g[(size_t)bq * EMB + h * 32 + pt * 2 + 1];

        // exact reference math: (r + o/norm)*dim - 0.5
        const float x = (rx + ox / fW) * fW - 0.5f;
        const float y = (ry + oy / fH) * fH - 0.5f;

        const float x0f = floorf(x), y0f = floorf(y);
        const float fx = x - x0f, fy = y - y0f;
        const int ix = (int)x0f, iy = (int)y0f;

        const float vx0 = (ix >= 0 && ix < W) ? 1.f : 0.f;
        const float vx1 = (ix + 1 >= 0 && ix + 1 < W) ? 1.f : 0.f;
        const float vy0 = (iy >= 0 && iy < H) ? 1.f : 0.f;
        const float vy1 = (iy + 1 >= 0 && iy + 1 < H) ? 1.f : 0.f;

        const int cx0 = min(max(ix, 0), W - 1);
        const int cx1 = min(max(ix + 1, 0), W - 1);
        const int cy0 = min(max(iy, 0), H - 1);
        const int cy1 = min(max(iy + 1, 0), H - 1);

        float4 w;
        w.x = (1.f - fx) * (1.f - fy) * aw * vx0 * vy0;
        w.y = fx * (1.f - fy) * aw * vx1 * vy0;
        w.z = (1.f - fx) * fy * aw * vx0 * vy1;
        w.w = fx * fy * aw * vx1 * vy1;

        const int base = c_ST[l];
        int4 o;
        o.x = (base + cy0 * W + cx0) * EMB;
        o.y = (base + cy0 * W + cx1) * EMB;
        o.z = (base + cy1 * W + cx0) * EMB;
        o.w = (base + cy1 * W + cx1) * EMB;

        s_w[wt][pt] = w;
        s_o[wt][pt] = o;
    }
    __syncthreads();

    // ---------------- Phase 2 ----------------
    const int lane  = tid & 31;
    const int wrp   = tid >> 5;
    const int lane2 = lane & 15;           // channel-pair index
    const int half  = lane >> 4;           // which of the 2 points
    const int task  = blockIdx.x * 8 + wrp;
    const int h  = task & 7;
    const int bq = task >> 3;
    const int b  = bq / NQ;

    const float* vt = v_g + ((size_t)b * NV) * EMB + h * 32 + lane2 * 2;

    float accx = 0.f, accy = 0.f;
    #pragma unroll
    for (int pb = 0; pb < 16; pb += 2) {
        const int mypt = pb + half;
        const float4 w = s_w[wrp][mypt];
        const int4   o = s_o[wrp][mypt];
        const float2 v00 = *reinterpret_cast<const float2*>(vt + o.x);
        const float2 v10 = *reinterpret_cast<const float2*>(vt + o.y);
        const float2 v01 = *reinterpret_cast<const float2*>(vt + o.z);
        const float2 v11 = *reinterpret_cast<const float2*>(vt + o.w);
        accx += w.x * v00.x + w.y * v10.x + w.z * v01.x + w.w * v11.x;
        accy += w.x * v00.y + w.y * v10.y + w.z * v01.y + w.w * v11.y;
    }

    // combine the two halves: lanes 0-15 hold even points, 16-31 odd points
    accx += __shfl_down_sync(0xffffffffu, accx, 16);
    accy += __shfl_down_sync(0xffffffffu, accy, 16);

    if (half == 0) {
        float2 r = make_float2(accx, accy);
        *reinterpret_cast<float2*>(
            mid_g + (size_t)bq * EMB + h * 32 + lane2 * 2) = r;
    }
}

// ---------------------------------------------------------------------------
extern "C" void kernel_launch(void* const* d_in, const int* in_sizes, int n_in,
                              void* d_out, int out_size)
{
    const float* query  = (const float*)d_in[0];
    const float* value  = (const float*)d_in[1];
    const float* refp   = (const float*)d_in[2];
    const float* W_off  = (const float*)d_in[4];
    const float* b_off  = (const float*)d_in[5];
    const float* W_attn = (const float*)d_in[6];
    const float* b_attn = (const float*)d_in[7];
    const float* W_val  = (const float*)d_in[8];
    const float* b_val  = (const float*)d_in[9];
    const float* W_out  = (const float*)d_in[10];
    const float* b_out  = (const float*)d_in[11];
    float* out = (float*)d_out;

    float *pv, *poff, *pattn, *pmid;
    cudaGetSymbolAddress((void**)&pv,    g_v);
    cudaGetSymbolAddress((void**)&poff,  g_off);
    cudaGetSymbolAddress((void**)&pattn, g_attn);
    cudaGetSymbolAddress((void**)&pmid,  g_mid);

    // 1. value projection: [53176,256] @ [256,256]
    gemm_tf32_bias<<<dim3(2, (M1 + 127) / 128), 256>>>(
        value, W_val, b_val, pv, M1, EMB);

    // 2a. sampling offsets: [16000,256] @ [256,256]
    gemm_tf32_bias<<<dim3(2, BQ / 128), 256>>>(
        query, W_off, b_off, poff, BQ, EMB);

    // 2b. attention logits: [16000,256] @ [256,128]
    gemm_tf32_bias<<<dim3(1, BQ / 128), 256>>>(
        query, W_attn, b_attn, pattn, BQ, 128);

    // 3. softmax + bilinear sampling + weighted accumulate
    ms_deform_sample<<<BQ * NH / 8, 256>>>(refp, poff, pattn, pv, pmid);

    // 4. output projection: [16000,256] @ [256,256]
    gemm_tf32_bias<<<dim3(2, BQ / 128), 256>>>(
        pmid, W_out, b_out, out, BQ, EMB);
}

// round 5
// speedup vs baseline: 3.5489x; 1.2459x over previous
#include <cuda_runtime.h>
#include <cuda_fp16.h>
#include <cstdint>

// Fixed problem geometry
#define BS   4
#define NQ   4000
#define EMB  256
#define NH   8
#define NLV  4
#define NP   4
#define HD   32
#define NV   13294            // 100*100 + 50*50 + 25*25 + 13*13
#define M1   (BS * NV)        // 53176 rows for value projection
#define BQ   (BS * NQ)        // 16000

// Scratch (device globals; no cudaMalloc allowed)
__device__ __half g_valh[(size_t)M1 * EMB];        // value input, fp16
__device__ __half g_qh[(size_t)BQ * EMB];          // query, fp16
__device__ __half g_vh[(size_t)M1 * EMB];          // projected value, fp16
__device__ float  g_off[(size_t)BQ * EMB];         // sampling offsets, fp32
__device__ float  g_attn[(size_t)BQ * 128];        // attn logits, fp32
__device__ __half g_midh[(size_t)BQ * EMB];        // sampled output, fp16
// transposed fp16 weights: Wt[n][k], k contiguous (K = 256)
__device__ __half g_WvalT[256 * 256];
__device__ __half g_WoffT[256 * 256];
__device__ __half g_WattnT[128 * 256];
__device__ __half g_WoutT[256 * 256];

// ---------------------------------------------------------------------------
// fp32 -> fp16 elementwise convert, 8 floats per thread
// ---------------------------------------------------------------------------
__global__ __launch_bounds__(256) void f2h_kernel(
    const float* __restrict__ in, __half* __restrict__ out)
{
    const size_t base = ((size_t)blockIdx.x * 256 + threadIdx.x) * 8;
    float4 a = *reinterpret_cast<const float4*>(in + base);
    float4 b = *reinterpret_cast<const float4*>(in + base + 4);
    __half2 h[4];
    h[0] = __floats2half2_rn(a.x, a.y);
    h[1] = __floats2half2_rn(a.z, a.w);
    h[2] = __floats2half2_rn(b.x, b.y);
    h[3] = __floats2half2_rn(b.z, b.w);
    *reinterpret_cast<uint4*>(out + base) = *reinterpret_cast<uint4*>(h);
}

// ---------------------------------------------------------------------------
// Weight transpose + convert: W[K=256][N] fp32 -> Wt[N][256] fp16
// ---------------------------------------------------------------------------
__global__ __launch_bounds__(256) void wtrans_kernel(
    const float* __restrict__ W, __half* __restrict__ Wt, int N)
{
    __shared__ float t[32][33];
    const int n0 = blockIdx.x * 32;
    const int k0 = blockIdx.y * 32;
    const int tx = threadIdx.x & 31;
    const int ty = threadIdx.x >> 5;      // 0..7
    #pragma unroll
    for (int i = 0; i < 4; i++)
        t[ty + i * 8][tx] = W[(size_t)(k0 + ty + i * 8) * N + n0 + tx];
    __syncthreads();
    #pragma unroll
    for (int i = 0; i < 4; i++)
        Wt[(size_t)(n0 + ty + i * 8) * 256 + k0 + tx] =
            __float2half(t[tx][ty + i * 8]);
}

// ---------------------------------------------------------------------------
// fp16 tensor-core GEMM: C[M,N] = A[M,256] @ Bt[N,256]^T + bias[N]
// BM=128, BN=128, BK=32, 256 threads (8 warps: 4 along M x 2 along N),
// warp tile 32x64 via m16n8k16.f16. cp.async double-buffered.
// smem row stride 40 halves (80 B): fragment LDS provably conflict-free.
// out_half != 0 -> store __half, else fp32.
// ---------------------------------------------------------------------------
__device__ __forceinline__ void mma_f16(float* c, const uint32_t* a,
                                        uint32_t b0, uint32_t b1) {
    asm volatile(
        "mma.sync.aligned.m16n8k16.row.col.f32.f16.f16.f32 "
        "{%0,%1,%2,%3},{%4,%5,%6,%7},{%8,%9},{%0,%1,%2,%3};"
        : "+f"(c[0]), "+f"(c[1]), "+f"(c[2]), "+f"(c[3])
        : "r"(a[0]), "r"(a[1]), "r"(a[2]), "r"(a[3]), "r"(b0), "r"(b1));
}

__device__ __forceinline__ void cpa16(uint32_t saddr, const void* g, bool p) {
    int sz = p ? 16 : 0;
    asm volatile("cp.async.cg.shared.global [%0], [%1], 16, %2;"
                 :: "r"(saddr), "l"(g), "r"(sz));
}

#define SSTRIDE 40   // halves

__global__ __launch_bounds__(256, 2) void gemm_f16_bias(
    const __half* __restrict__ A, const __half* __restrict__ Bt,
    const float* __restrict__ bias, void* __restrict__ Cv,
    int M, int N, int out_half)   // K = 256 fixed
{
    __shared__ __align__(16) __half As[2][128][SSTRIDE];
    __shared__ __align__(16) __half Bs[2][128][SSTRIDE];

    const int tid  = threadIdx.x;
    const int lane = tid & 31, warp = tid >> 5;
    const int gid  = lane >> 2, tig = lane & 3;
    const int row0 = blockIdx.y * 128;
    const int col0 = blockIdx.x * 128;

    const uint32_t asb = (uint32_t)__cvta_generic_to_shared(&As[0][0][0]);
    const uint32_t bsb = (uint32_t)__cvta_generic_to_shared(&Bs[0][0][0]);

    // loader mapping: tile = 128 rows x 32 halves; 4 x 16B chunks per row.
    // thread handles chunks tid and tid+256 (512 chunks total per operand).
    float acc[2][8][4] = {};

    auto load_stage = [&](int st, int kb) {
        #pragma unroll
        for (int c = 0; c < 2; c++) {
            const int ci  = tid + c * 256;
            const int row = ci >> 2;
            const int ko  = (ci & 3) * 8;
            cpa16(asb + (((st * 128 + row) * SSTRIDE + ko) << 1),
                  A + (size_t)(row0 + row) * 256 + kb * 32 + ko,
                  row0 + row < M);
            cpa16(bsb + (((st * 128 + row) * SSTRIDE + ko) << 1),
                  Bt + (size_t)(col0 + row) * 256 + kb * 32 + ko, true);
        }
    };

    load_stage(0, 0);
    asm volatile("cp.async.commit_group;" ::: "memory");

    const int wm = (warp & 3) * 32;
    const int wn = (warp >> 2) * 64;

    for (int kb = 0; kb < 8; kb++) {
        asm volatile("cp.async.wait_group 0;" ::: "memory");
        __syncthreads();
        if (kb + 1 < 8) {
            load_stage((kb + 1) & 1, kb + 1);
            asm volatile("cp.async.commit_group;" ::: "memory");
        }
        const int st = kb & 1;

        #pragma unroll
        for (int ks = 0; ks < 32; ks += 16) {
            uint32_t a[2][4];
            #pragma unroll
            for (int mt = 0; mt < 2; mt++) {
                const int m0 = wm + mt * 16;
                a[mt][0] = *(const uint32_t*)&As[st][m0 + gid][ks + 2 * tig];
                a[mt][1] = *(const uint32_t*)&As[st][m0 + gid + 8][ks + 2 * tig];
                a[mt][2] = *(const uint32_t*)&As[st][m0 + gid][ks + 2 * tig + 8];
                a[mt][3] = *(const uint32_t*)&As[st][m0 + gid + 8][ks + 2 * tig + 8];
            }
            #pragma unroll
            for (int nt = 0; nt < 8; nt++) {
                const int nn = wn + nt * 8 + gid;
                uint32_t b0 = *(const uint32_t*)&Bs[st][nn][ks + 2 * tig];
                uint32_t b1 = *(const uint32_t*)&Bs[st][nn][ks + 2 * tig + 8];
                mma_f16(acc[0][nt], a[0], b0, b1);
                mma_f16(acc[1][nt], a[1], b0, b1);
            }
        }
        __syncthreads();
    }

    // epilogue: per-thread cols are contiguous pairs (tig*2, tig*2+1)
    #pragma unroll
    for (int mt = 0; mt < 2; mt++) {
        const int rbase = row0 + wm + mt * 16 + gid;
        #pragma unroll
        for (int nt = 0; nt < 8; nt++) {
            const int col = col0 + wn + nt * 8 + tig * 2;
            const float b0 = bias[col], b1 = bias[col + 1];
            if (out_half) {
                __half* C = (__half*)Cv;
                if (rbase < M)
                    *reinterpret_cast<__half2*>(&C[(size_t)rbase * N + col]) =
                        __floats2half2_rn(acc[mt][nt][0] + b0, acc[mt][nt][1] + b1);
                if (rbase + 8 < M)
                    *reinterpret_cast<__half2*>(&C[(size_t)(rbase + 8) * N + col]) =
                        __floats2half2_rn(acc[mt][nt][2] + b0, acc[mt][nt][3] + b1);
            } else {
                float* C = (float*)Cv;
                if (rbase < M) {
                    C[(size_t)rbase * N + col]     = acc[mt][nt][0] + b0;
                    C[(size_t)rbase * N + col + 1] = acc[mt][nt][1] + b1;
                }
                if (rbase + 8 < M) {
                    C[(size_t)(rbase + 8) * N + col]     = acc[mt][nt][2] + b0;
                    C[(size_t)(rbase + 8) * N + col + 1] = acc[mt][nt][3] + b1;
                }
            }
        }
    }
}

// ---------------------------------------------------------------------------
// Sampling kernel, two-phase; v and mid are fp16 (half2 per lane = 2 ch).
// ---------------------------------------------------------------------------
__constant__ int c_HH[4] = {100, 50, 25, 13};
__constant__ int c_ST[4] = {0, 10000, 12500, 13125};

__global__ __launch_bounds__(256) void ms_deform_sample(
    const float* __restrict__ refp_g, const float* __restrict__ off_g,
    const float* __restrict__ attn_g, const __half2* __restrict__ v_g,
    __half* __restrict__ mid_g)
{
    __shared__ float4 s_w[8][16];
    __shared__ int4   s_o[8][16];

    const int tid = threadIdx.x;

    // ---------------- Phase 1 ----------------
    if (tid < 128) {
        const int wt = tid >> 4;            // local task 0..7
        const int pt = tid & 15;            // point 0..15
        const int task = blockIdx.x * 8 + wt;
        const int h  = task & 7;
        const int bq = task >> 3;

        const float* lg = attn_g + (size_t)bq * (NH * 16) + h * 16;
        float mx = -1e30f;
        #pragma unroll
        for (int i = 0; i < 16; i++) mx = fmaxf(mx, lg[i]);
        float s = 0.f;
        #pragma unroll
        for (int i = 0; i < 16; i++) s += __expf(lg[i] - mx);
        const float aw = __expf(lg[pt] - mx) / s;

        const int l = pt >> 2;
        const int W = c_HH[l];
        const int H = W;
        const float fW = (float)W, fH = (float)H;

        const float rx = refp_g[(size_t)bq * (NLV * 2) + l * 2 + 0];
        const float ry = refp_g[(size_t)bq * (NLV * 2) + l * 2 + 1];
        const float ox = off_g[(size_t)bq * EMB + h * 32 + pt * 2 + 0];
        const float oy = off_g[(size_t)bq * EMB + h * 32 + pt * 2 + 1];

        // exact reference math: (r + o/norm)*dim - 0.5
        const float x = (rx + ox / fW) * fW - 0.5f;
        const float y = (ry + oy / fH) * fH - 0.5f;

        const float x0f = floorf(x), y0f = floorf(y);
        const float fx = x - x0f, fy = y - y0f;
        const int ix = (int)x0f, iy = (int)y0f;

        const float vx0 = (ix >= 0 && ix < W) ? 1.f : 0.f;
        const float vx1 = (ix + 1 >= 0 && ix + 1 < W) ? 1.f : 0.f;
        const float vy0 = (iy >= 0 && iy < H) ? 1.f : 0.f;
        const float vy1 = (iy + 1 >= 0 && iy + 1 < H) ? 1.f : 0.f;

        const int cx0 = min(max(ix, 0), W - 1);
        const int cx1 = min(max(ix + 1, 0), W - 1);
        const int cy0 = min(max(iy, 0), H - 1);
        const int cy1 = min(max(iy + 1, 0), H - 1);

        float4 w;
        w.x = (1.f - fx) * (1.f - fy) * aw * vx0 * vy0;
        w.y = fx * (1.f - fy) * aw * vx1 * vy0;
        w.z = (1.f - fx) * fy * aw * vx0 * vy1;
        w.w = fx * fy * aw * vx1 * vy1;

        const int base = c_ST[l];
        int4 o;                              // offsets in half2 units (128/token)
        o.x = (base + cy0 * W + cx0) * 128;
        o.y = (base + cy0 * W + cx1) * 128;
        o.z = (base + cy1 * W + cx0) * 128;
        o.w = (base + cy1 * W + cx1) * 128;

        s_w[wt][pt] = w;
        s_o[wt][pt] = o;
    }
    __syncthreads();

    // ---------------- Phase 2 ----------------
    const int lane  = tid & 31;
    const int wrp   = tid >> 5;
    const int lane2 = lane & 15;           // half2 (channel-pair) index
    const int half  = lane >> 4;           // which of the 2 points
    const int task  = blockIdx.x * 8 + wrp;
    const int h  = task & 7;
    const int bq = task >> 3;
    const int b  = bq / NQ;

    const __half2* vt = v_g + (size_t)b * NV * 128 + h * 16 + lane2;

    float accx = 0.f, accy = 0.f;
    #pragma unroll
    for (int pb = 0; pb < 16; pb += 2) {
        const int mypt = pb + half;
        const float4 w = s_w[wrp][mypt];
        const int4   o = s_o[wrp][mypt];
        const float2 v00 = __half22float2(vt[o.x]);
        const float2 v10 = __half22float2(vt[o.y]);
        const float2 v01 = __half22float2(vt[o.z]);
        const float2 v11 = __half22float2(vt[o.w]);
        accx += w.x * v00.x + w.y * v10.x + w.z * v01.x + w.w * v11.x;
        accy += w.x * v00.y + w.y * v10.y + w.z * v01.y + w.w * v11.y;
    }

    accx += __shfl_down_sync(0xffffffffu, accx, 16);
    accy += __shfl_down_sync(0xffffffffu, accy, 16);

    if (half == 0) {
        *reinterpret_cast<__half2*>(
            mid_g + (size_t)bq * EMB + h * 32 + lane2 * 2) =
            __floats2half2_rn(accx, accy);
    }
}

// ---------------------------------------------------------------------------
extern "C" void kernel_launch(void* const* d_in, const int* in_sizes, int n_in,
                              void* d_out, int out_size)
{
    const float* query  = (const float*)d_in[0];
    const float* value  = (const float*)d_in[1];
    const float* refp   = (const float*)d_in[2];
    const float* W_off  = (const float*)d_in[4];
    const float* b_off  = (const float*)d_in[5];
    const float* W_attn = (const float*)d_in[6];
    const float* b_attn = (const float*)d_in[7];
    const float* W_val  = (const float*)d_in[8];
    const float* b_val  = (const float*)d_in[9];
    const float* W_out  = (const float*)d_in[10];
    const float* b_out  = (const float*)d_in[11];
    float* out = (float*)d_out;

    __half *pvalh, *pqh, *pvh, *pmidh, *pWvalT, *pWoffT, *pWattnT, *pWoutT;
    float *poff, *pattn;
    cudaGetSymbolAddress((void**)&pvalh,  g_valh);
    cudaGetSymbolAddress((void**)&pqh,    g_qh);
    cudaGetSymbolAddress((void**)&pvh,    g_vh);
    cudaGetSymbolAddress((void**)&poff,   g_off);
    cudaGetSymbolAddress((void**)&pattn,  g_attn);
    cudaGetSymbolAddress((void**)&pmidh,  g_midh);
    cudaGetSymbolAddress((void**)&pWvalT, g_WvalT);
    cudaGetSymbolAddress((void**)&pWoffT, g_WoffT);
    cudaGetSymbolAddress((void**)&pWattnT, g_WattnT);
    cudaGetSymbolAddress((void**)&pWoutT, g_WoutT);

    // 0. conversions
    f2h_kernel<<<(M1 * EMB) / (256 * 8), 256>>>(value, pvalh);
    f2h_kernel<<<(BQ * EMB) / (256 * 8), 256>>>(query, pqh);
    wtrans_kernel<<<dim3(8, 8), 256>>>(W_val,  pWvalT, 256);
    wtrans_kernel<<<dim3(8, 8), 256>>>(W_off,  pWoffT, 256);
    wtrans_kernel<<<dim3(4, 8), 256>>>(W_attn, pWattnT, 128);
    wtrans_kernel<<<dim3(8, 8), 256>>>(W_out,  pWoutT, 256);

    // 1. value projection: [53176,256] @ [256,256] -> fp16
    gemm_f16_bias<<<dim3(2, (M1 + 127) / 128), 256>>>(
        pvalh, pWvalT, b_val, pvh, M1, EMB, 1);

    // 2a. sampling offsets: [16000,256] @ [256,256] -> fp32
    gemm_f16_bias<<<dim3(2, BQ / 128), 256>>>(
        pqh, pWoffT, b_off, poff, BQ, EMB, 0);

    // 2b. attention logits: [16000,256] @ [256,128] -> fp32
    gemm_f16_bias<<<dim3(1, BQ / 128), 256>>>(
        pqh, pWattnT, b_attn, pattn, BQ, 128, 0);

    // 3. softmax + bilinear sampling + weighted accumulate -> fp16 mid
    ms_deform_sample<<<BQ * NH / 8, 256>>>(
        refp, poff, pattn, (const __half2*)pvh, pmidh);

    // 4. output projection: [16000,256] @ [256,256] -> fp32 out
    gemm_f16_bias<<<dim3(2, BQ / 128), 256>>>(
        pmidh, pWoutT, b_out, out, BQ, EMB, 0);
}